// round 6
// baseline (speedup 1.0000x reference)
#include <cuda_runtime.h>
#include <cuda_fp16.h>
#include <math.h>

// Problem constants (fixed by the reference)
#define VOCAB  100000
#define DIM    128
#define BATCH  4096
#define CTX    10
#define NNEG   200   // CTX * N_NEGS
#define FULL   0xffffffffu

// fp16 scratch copy of emb_o, rebuilt every launch (25.6 MB)
__device__ __half g_emb_o_h[(size_t)VOCAB * DIM];

__device__ __forceinline__ float log_sigmoid(float x) {
    float ax = fabsf(x);
    return fminf(x, 0.0f) - __logf(1.0f + __expf(-ax));
}

// 4-half lane slice -> dot with 4-float iv slice
__device__ __forceinline__ float dot4h(const float4 iv, uint2 hv) {
    __half2 h01 = *reinterpret_cast<__half2*>(&hv.x);
    __half2 h23 = *reinterpret_cast<__half2*>(&hv.y);
    float2 f01 = __half22float2(h01);
    float2 f23 = __half22float2(h23);
    return fmaf(iv.x, f01.x, fmaf(iv.y, f01.y, fmaf(iv.z, f23.x, iv.w * f23.y)));
}

// Merge two per-lane partial-sum sets across the `bit` butterfly.
__device__ __forceinline__ float merge2(float a, float b, int lane, int bit) {
    float send = (lane & bit) ? a : b;
    float recv = __shfl_xor_sync(FULL, send, bit);
    float keep = (lane & bit) ? b : a;
    return keep + recv;
}

// Reduce 8 independent per-lane partial sums; each row's sum lands in 4 lanes.
__device__ __forceinline__ float reduce8(const float p[8], int lane) {
    float m0 = merge2(p[0], p[1], lane, 16);
    float m1 = merge2(p[2], p[3], lane, 16);
    float m2 = merge2(p[4], p[5], lane, 16);
    float m3 = merge2(p[6], p[7], lane, 16);
    float n0 = merge2(m0, m1, lane, 8);
    float n1 = merge2(m2, m3, lane, 8);
    float r  = merge2(n0, n1, lane, 4);
    r += __shfl_xor_sync(FULL, r, 2);
    r += __shfl_xor_sync(FULL, r, 1);
    return r;
}

// Reduce 16 independent per-lane partial sums; each row's sum lands in 2 lanes.
// 15 merges + 1 butterfly = 16 shuffles per 16 rows.
__device__ __forceinline__ float reduce16(const float p[16], int lane) {
    float m[8];
#pragma unroll
    for (int i = 0; i < 8; i++) m[i] = merge2(p[2 * i], p[2 * i + 1], lane, 16);
    float n[4];
#pragma unroll
    for (int i = 0; i < 4; i++) n[i] = merge2(m[2 * i], m[2 * i + 1], lane, 8);
    float q0 = merge2(n[0], n[1], lane, 4);
    float q1 = merge2(n[2], n[3], lane, 4);
    float r  = merge2(q0, q1, lane, 2);
    r += __shfl_xor_sync(FULL, r, 1);
    return r;
}

// fp32 -> fp16 table conversion (streaming); thread 0 also zeroes the output.
__global__ __launch_bounds__(256)
void sgns_convert(const float4* __restrict__ src, float* __restrict__ out) {
    const int n4 = VOCAB * DIM / 4;  // 3,200,000
    int i = blockIdx.x * blockDim.x + threadIdx.x;
    if (i == 0) out[0] = 0.0f;
    if (i < n4) {
        float4 v = __ldg(src + i);
        __half2 a = __floats2half2_rn(v.x, v.y);
        __half2 b = __floats2half2_rn(v.z, v.w);
        uint2 o;
        o.x = *reinterpret_cast<unsigned*>(&a);
        o.y = *reinterpret_cast<unsigned*>(&b);
        reinterpret_cast<uint2*>(g_emb_o_h)[i] = o;
    }
}

__device__ __forceinline__ const uint2* row_h(int idx) {
    return reinterpret_cast<const uint2*>(g_emb_o_h) + (size_t)idx * (DIM / 4);
}

__global__ __launch_bounds__(256)
void sgns_kernel(const float* __restrict__ emb_i,
                 const int*   __restrict__ iword,
                 const int*   __restrict__ owords,
                 const int*   __restrict__ nwords,
                 float*       __restrict__ out) {
    const int warp = (blockIdx.x * blockDim.x + threadIdx.x) >> 5;
    const int lane = threadIdx.x & 31;
    if (warp >= BATCH) return;

    const float4 iv =
        *reinterpret_cast<const float4*>(emb_i + (size_t)iword[warp] * DIM + lane * 4);

    const int* __restrict__ ow = owords + warp * CTX;
    const int* __restrict__ nw = nwords + warp * NNEG;

    float acc2 = 0.0f;   // rows counted 2x across the warp (reduce16 path)
    float acc4 = 0.0f;   // rows counted 4x across the warp (reduce8 path)
    float accU = 0.0f;   // rows counted once (lane-uniform)

    // ---- positives: 8 batched + 2 classic ----
    {
        float p[8];
#pragma unroll
        for (int c = 0; c < 8; c++) {
            uint2 hv = __ldg(row_h(ow[c]) + lane);
            p[c] = dot4h(iv, hv);
        }
        acc4 += log_sigmoid(reduce8(p, lane));

#pragma unroll
        for (int c = 8; c < CTX; c++) {
            uint2 hv = __ldg(row_h(ow[c]) + lane);
            float s = dot4h(iv, hv);
            s += __shfl_xor_sync(FULL, s, 16);
            s += __shfl_xor_sync(FULL, s, 8);
            s += __shfl_xor_sync(FULL, s, 4);
            s += __shfl_xor_sync(FULL, s, 2);
            s += __shfl_xor_sync(FULL, s, 1);
            accU += log_sigmoid(s);
        }
    }

    // ---- negatives: 12 batches of 16 rows (16 loads in flight = 4KB/warp) ----
    for (int k = 0; k < 192; k += 16) {
        const int4 ia = *reinterpret_cast<const int4*>(nw + k);
        const int4 ib = *reinterpret_cast<const int4*>(nw + k + 4);
        const int4 ic = *reinterpret_cast<const int4*>(nw + k + 8);
        const int4 id = *reinterpret_cast<const int4*>(nw + k + 12);

        uint2 v[16];
        v[0]  = __ldg(row_h(ia.x) + lane);
        v[1]  = __ldg(row_h(ia.y) + lane);
        v[2]  = __ldg(row_h(ia.z) + lane);
        v[3]  = __ldg(row_h(ia.w) + lane);
        v[4]  = __ldg(row_h(ib.x) + lane);
        v[5]  = __ldg(row_h(ib.y) + lane);
        v[6]  = __ldg(row_h(ib.z) + lane);
        v[7]  = __ldg(row_h(ib.w) + lane);
        v[8]  = __ldg(row_h(ic.x) + lane);
        v[9]  = __ldg(row_h(ic.y) + lane);
        v[10] = __ldg(row_h(ic.z) + lane);
        v[11] = __ldg(row_h(ic.w) + lane);
        v[12] = __ldg(row_h(id.x) + lane);
        v[13] = __ldg(row_h(id.y) + lane);
        v[14] = __ldg(row_h(id.z) + lane);
        v[15] = __ldg(row_h(id.w) + lane);

        float p[16];
#pragma unroll
        for (int i = 0; i < 16; i++) p[i] = dot4h(iv, v[i]);

        acc2 += log_sigmoid(-reduce16(p, lane));
    }

    // ---- remaining 8 negatives ----
    {
        const int4 ia = *reinterpret_cast<const int4*>(nw + 192);
        const int4 ib = *reinterpret_cast<const int4*>(nw + 196);
        uint2 v0 = __ldg(row_h(ia.x) + lane);
        uint2 v1 = __ldg(row_h(ia.y) + lane);
        uint2 v2 = __ldg(row_h(ia.z) + lane);
        uint2 v3 = __ldg(row_h(ia.w) + lane);
        uint2 v4 = __ldg(row_h(ib.x) + lane);
        uint2 v5 = __ldg(row_h(ib.y) + lane);
        uint2 v6 = __ldg(row_h(ib.z) + lane);
        uint2 v7 = __ldg(row_h(ib.w) + lane);
        float p[8];
        p[0] = dot4h(iv, v0); p[1] = dot4h(iv, v1);
        p[2] = dot4h(iv, v2); p[3] = dot4h(iv, v3);
        p[4] = dot4h(iv, v4); p[5] = dot4h(iv, v5);
        p[6] = dot4h(iv, v6); p[7] = dot4h(iv, v7);
        acc4 += log_sigmoid(-reduce8(p, lane));
    }

    // Combine: rows in acc2 counted 2x, acc4 counted 4x, accU once.
    float a = fmaf(acc2, 0.5f, acc4 * 0.25f);
    a += __shfl_xor_sync(FULL, a, 16);
    a += __shfl_xor_sync(FULL, a, 8);
    a += __shfl_xor_sync(FULL, a, 4);
    a += __shfl_xor_sync(FULL, a, 2);
    a += __shfl_xor_sync(FULL, a, 1);
    float total = a + accU;

    if (lane == 0) {
        atomicAdd(out, -total * (1.0f / (float)(CTX * BATCH)));
    }
}

extern "C" void kernel_launch(void* const* d_in, const int* in_sizes, int n_in,
                              void* d_out, int out_size) {
    const float* emb_i  = (const float*)d_in[0];
    const float* emb_o  = (const float*)d_in[1];
    const int*   iword  = (const int*)d_in[2];
    const int*   owords = (const int*)d_in[3];
    const int*   nwords = (const int*)d_in[4];
    float* out = (float*)d_out;

    // Convert emb_o to fp16 scratch table (also zeroes out[0])
    const int n4 = VOCAB * DIM / 4;
    sgns_convert<<<(n4 + 255) / 256, 256>>>(reinterpret_cast<const float4*>(emb_o), out);

    // Main: 1 warp per batch row
    const int threads = 256;
    const int blocks = (BATCH + (threads / 32) - 1) / (threads / 32);
    sgns_kernel<<<blocks, threads>>>(emb_i, iword, owords, nwords, out);
}

// round 8
// speedup vs baseline: 1.2257x; 1.2257x over previous
#include <cuda_runtime.h>
#include <cuda_fp16.h>
#include <math.h>

// Problem constants (fixed by the reference)
#define VOCAB  100000
#define DIM    128
#define BATCH  4096
#define CTX    10
#define NNEG   200   // CTX * N_NEGS
#define FULL   0xffffffffu

// fp16 scratch copy of emb_o, rebuilt every launch (25.6 MB)
__device__ __half g_emb_o_h[(size_t)VOCAB * DIM];

__device__ __forceinline__ float log_sigmoid(float x) {
    float ax = fabsf(x);
    return fminf(x, 0.0f) - __logf(1.0f + __expf(-ax));
}

__device__ __forceinline__ const uint4* row_h4(int idx) {
    // row as 16 uint4 chunks (8 halves each)
    return reinterpret_cast<const uint4*>(g_emb_o_h) + (size_t)idx * (DIM / 8);
}

// dot of lane's 8 fp32 iv elems with 8 packed halves
__device__ __forceinline__ float dot8h(const float iv[8], uint4 hv) {
    float2 f0 = __half22float2(*reinterpret_cast<__half2*>(&hv.x));
    float2 f1 = __half22float2(*reinterpret_cast<__half2*>(&hv.y));
    float2 f2 = __half22float2(*reinterpret_cast<__half2*>(&hv.z));
    float2 f3 = __half22float2(*reinterpret_cast<__half2*>(&hv.w));
    float s = iv[0] * f0.x;
    s = fmaf(iv[1], f0.y, s);
    s = fmaf(iv[2], f1.x, s);
    s = fmaf(iv[3], f1.y, s);
    s = fmaf(iv[4], f2.x, s);
    s = fmaf(iv[5], f2.y, s);
    s = fmaf(iv[6], f3.x, s);
    s = fmaf(iv[7], f3.y, s);
    return s;
}

// Merge two per-lane partial-sum sets across the `bit` butterfly.
__device__ __forceinline__ float merge2(float a, float b, int lane, int bit) {
    float send = (lane & bit) ? a : b;
    float recv = __shfl_xor_sync(FULL, send, bit);
    float keep = (lane & bit) ? b : a;
    return keep + recv;
}

// 8 partials per lane, rows live in 16-lane halves (bits 8,4,2,1).
// Returns full row sum; each row's sum lands in 2 lanes.
__device__ __forceinline__ float reduce8h(const float p[8], int lane) {
    float m0 = merge2(p[0], p[1], lane, 8);
    float m1 = merge2(p[2], p[3], lane, 8);
    float m2 = merge2(p[4], p[5], lane, 8);
    float m3 = merge2(p[6], p[7], lane, 8);
    float n0 = merge2(m0, m1, lane, 4);
    float n1 = merge2(m2, m3, lane, 4);
    float r  = merge2(n0, n1, lane, 2);
    r += __shfl_xor_sync(FULL, r, 1);
    return r;
}

// 4 partials per lane (8 rows); each row's sum lands in 4 lanes.
__device__ __forceinline__ float reduce4h(const float p[4], int lane) {
    float m0 = merge2(p[0], p[1], lane, 8);
    float m1 = merge2(p[2], p[3], lane, 8);
    float r  = merge2(m0, m1, lane, 4);
    r += __shfl_xor_sync(FULL, r, 2);
    r += __shfl_xor_sync(FULL, r, 1);
    return r;
}

// fp32 -> fp16 table conversion (streaming); thread 0 also zeroes the output.
__global__ __launch_bounds__(256)
void sgns_convert(const float4* __restrict__ src, float* __restrict__ out) {
    const int n4 = VOCAB * DIM / 4;  // 3,200,000
    int i = blockIdx.x * blockDim.x + threadIdx.x;
    if (i == 0) out[0] = 0.0f;
    if (i < n4) {
        float4 v = __ldg(src + i);
        __half2 a = __floats2half2_rn(v.x, v.y);
        __half2 b = __floats2half2_rn(v.z, v.w);
        uint2 o;
        o.x = *reinterpret_cast<unsigned*>(&a);
        o.y = *reinterpret_cast<unsigned*>(&b);
        reinterpret_cast<uint2*>(g_emb_o_h)[i] = o;
    }
}

// 1 warp per batch row; half-warp per embedding row (uint4 = 8 halves per lane).
__global__ __launch_bounds__(128, 6)
void sgns_kernel(const float* __restrict__ emb_i,
                 const int*   __restrict__ iword,
                 const int*   __restrict__ owords,
                 const int*   __restrict__ nwords,
                 float*       __restrict__ out) {
    const int warp = (blockIdx.x * blockDim.x + threadIdx.x) >> 5;
    const int lane = threadIdx.x & 31;
    if (warp >= BATCH) return;
    const int hi  = lane >> 4;    // which of the 2 rows per load
    const int l15 = lane & 15;    // position within the row (16B chunk)

    // iv: this lane's 8-float slice of the input-word vector
    const float* ivp = emb_i + (size_t)iword[warp] * DIM + l15 * 8;
    const float4 a0 = *reinterpret_cast<const float4*>(ivp);
    const float4 a1 = *reinterpret_cast<const float4*>(ivp + 4);
    float iv[8] = {a0.x, a0.y, a0.z, a0.w, a1.x, a1.y, a1.z, a1.w};

    const int* __restrict__ ow = owords + warp * CTX;   // only 8-byte aligned; scalar loads
    const int* __restrict__ nw = nwords + warp * NNEG;  // 16-byte aligned (200*4B)

    float acc2  = 0.0f;   // rows counted 2x across the warp
    float acc4  = 0.0f;   // rows counted 4x
    float acc16 = 0.0f;   // rows counted 16x (uniform within half)

    // ---- positives: 10 rows = 5 warp-loads (scalar index loads: ow is not 16B-aligned) ----
    {
        int i0 = ow[0 + hi];
        int i1 = ow[2 + hi];
        int i2 = ow[4 + hi];
        int i3 = ow[6 + hi];
        int i4 = ow[8 + hi];
        uint4 v0 = __ldg(row_h4(i0) + l15);
        uint4 v1 = __ldg(row_h4(i1) + l15);
        uint4 v2 = __ldg(row_h4(i2) + l15);
        uint4 v3 = __ldg(row_h4(i3) + l15);
        uint4 v4 = __ldg(row_h4(i4) + l15);

        float p[4];
        p[0] = dot8h(iv, v0); p[1] = dot8h(iv, v1);
        p[2] = dot8h(iv, v2); p[3] = dot8h(iv, v3);
        acc4 += log_sigmoid(reduce4h(p, lane));

        float q = dot8h(iv, v4);
        q += __shfl_xor_sync(FULL, q, 8);
        q += __shfl_xor_sync(FULL, q, 4);
        q += __shfl_xor_sync(FULL, q, 2);
        q += __shfl_xor_sync(FULL, q, 1);
        acc16 += log_sigmoid(q);   // uniform within half
    }

    // ---- negatives: 12 batches of 16 rows (8 LDG.128 in flight = 4KB/warp) ----
#pragma unroll 2
    for (int k = 0; k < 192; k += 16) {
        const int4 ia = *reinterpret_cast<const int4*>(nw + k);
        const int4 ib = *reinterpret_cast<const int4*>(nw + k + 4);
        const int4 ic = *reinterpret_cast<const int4*>(nw + k + 8);
        const int4 id = *reinterpret_cast<const int4*>(nw + k + 12);
        int i0 = hi ? ia.y : ia.x;
        int i1 = hi ? ia.w : ia.z;
        int i2 = hi ? ib.y : ib.x;
        int i3 = hi ? ib.w : ib.z;
        int i4 = hi ? ic.y : ic.x;
        int i5 = hi ? ic.w : ic.z;
        int i6 = hi ? id.y : id.x;
        int i7 = hi ? id.w : id.z;

        uint4 v0 = __ldg(row_h4(i0) + l15);
        uint4 v1 = __ldg(row_h4(i1) + l15);
        uint4 v2 = __ldg(row_h4(i2) + l15);
        uint4 v3 = __ldg(row_h4(i3) + l15);
        uint4 v4 = __ldg(row_h4(i4) + l15);
        uint4 v5 = __ldg(row_h4(i5) + l15);
        uint4 v6 = __ldg(row_h4(i6) + l15);
        uint4 v7 = __ldg(row_h4(i7) + l15);

        float p[8];
        p[0] = dot8h(iv, v0); p[1] = dot8h(iv, v1);
        p[2] = dot8h(iv, v2); p[3] = dot8h(iv, v3);
        p[4] = dot8h(iv, v4); p[5] = dot8h(iv, v5);
        p[6] = dot8h(iv, v6); p[7] = dot8h(iv, v7);

        acc2 += log_sigmoid(-reduce8h(p, lane));
    }

    // ---- remaining 8 negatives: 4 warp-loads ----
    {
        const int4 ia = *reinterpret_cast<const int4*>(nw + 192);
        const int4 ib = *reinterpret_cast<const int4*>(nw + 196);
        int i0 = hi ? ia.y : ia.x;
        int i1 = hi ? ia.w : ia.z;
        int i2 = hi ? ib.y : ib.x;
        int i3 = hi ? ib.w : ib.z;
        uint4 v0 = __ldg(row_h4(i0) + l15);
        uint4 v1 = __ldg(row_h4(i1) + l15);
        uint4 v2 = __ldg(row_h4(i2) + l15);
        uint4 v3 = __ldg(row_h4(i3) + l15);
        float p[4];
        p[0] = dot8h(iv, v0); p[1] = dot8h(iv, v1);
        p[2] = dot8h(iv, v2); p[3] = dot8h(iv, v3);
        acc4 += log_sigmoid(-reduce4h(p, lane));
    }

    // Combine redundancy-weighted accumulators, then full-warp sum.
    float a = fmaf(acc2, 0.5f, fmaf(acc4, 0.25f, acc16 * 0.0625f));
    a += __shfl_xor_sync(FULL, a, 16);
    a += __shfl_xor_sync(FULL, a, 8);
    a += __shfl_xor_sync(FULL, a, 4);
    a += __shfl_xor_sync(FULL, a, 2);
    a += __shfl_xor_sync(FULL, a, 1);

    if (lane == 0) {
        atomicAdd(out, -a * (1.0f / (float)(CTX * BATCH)));
    }
}

extern "C" void kernel_launch(void* const* d_in, const int* in_sizes, int n_in,
                              void* d_out, int out_size) {
    const float* emb_i  = (const float*)d_in[0];
    const float* emb_o  = (const float*)d_in[1];
    const int*   iword  = (const int*)d_in[2];
    const int*   owords = (const int*)d_in[3];
    const int*   nwords = (const int*)d_in[4];
    float* out = (float*)d_out;

    // Convert emb_o to fp16 scratch table (also zeroes out[0])
    const int n4 = VOCAB * DIM / 4;
    sgns_convert<<<(n4 + 255) / 256, 256>>>(reinterpret_cast<const float4*>(emb_o), out);

    // Main: 1 warp per batch row, 128-thread blocks for fine wave packing
    const int threads = 128;
    const int blocks = BATCH * 32 / threads;  // 1024
    sgns_kernel<<<blocks, threads>>>(emb_i, iword, owords, nwords, out);
}

// round 9
// speedup vs baseline: 1.3776x; 1.1239x over previous
#include <cuda_runtime.h>
#include <cuda_fp16.h>
#include <math.h>

// Problem constants (fixed by the reference)
#define VOCAB  100000
#define DIM    128
#define BATCH  4096
#define CTX    10
#define NNEG   200   // CTX * N_NEGS
#define FULL   0xffffffffu

// fp16 scratch copy of emb_o, rebuilt every launch (25.6 MB)
__device__ __half g_emb_o_h[(size_t)VOCAB * DIM];

__device__ __forceinline__ float log_sigmoid(float x) {
    float ax = fabsf(x);
    return fminf(x, 0.0f) - __logf(1.0f + __expf(-ax));
}

__device__ __forceinline__ const uint4* row_h4(int idx) {
    // row as 16 uint4 chunks (8 halves each)
    return reinterpret_cast<const uint4*>(g_emb_o_h) + (size_t)idx * (DIM / 8);
}

// dot of lane's 8 iv halves (4x half2) with 8 packed halves; fp16 accumulate,
// fp32 finish.
__device__ __forceinline__ float dot8h2(const __half2 iv[4], uint4 hv) {
    __half2 h0 = *reinterpret_cast<__half2*>(&hv.x);
    __half2 h1 = *reinterpret_cast<__half2*>(&hv.y);
    __half2 h2 = *reinterpret_cast<__half2*>(&hv.z);
    __half2 h3 = *reinterpret_cast<__half2*>(&hv.w);
    __half2 acc = __hmul2(iv[0], h0);
    acc = __hfma2(iv[1], h1, acc);
    acc = __hfma2(iv[2], h2, acc);
    acc = __hfma2(iv[3], h3, acc);
    float2 f = __half22float2(acc);
    return f.x + f.y;
}

// Merge two per-lane partial-sum sets across the `bit` butterfly.
__device__ __forceinline__ float merge2(float a, float b, int lane, int bit) {
    float send = (lane & bit) ? a : b;
    float recv = __shfl_xor_sync(FULL, send, bit);
    float keep = (lane & bit) ? b : a;
    return keep + recv;
}

// 8 partials per lane, rows live in 16-lane halves (bits 8,4,2,1).
__device__ __forceinline__ float reduce8h(const float p[8], int lane) {
    float m0 = merge2(p[0], p[1], lane, 8);
    float m1 = merge2(p[2], p[3], lane, 8);
    float m2 = merge2(p[4], p[5], lane, 8);
    float m3 = merge2(p[6], p[7], lane, 8);
    float n0 = merge2(m0, m1, lane, 4);
    float n1 = merge2(m2, m3, lane, 4);
    float r  = merge2(n0, n1, lane, 2);
    r += __shfl_xor_sync(FULL, r, 1);
    return r;
}

// 4 partials per lane (8 rows); each row's sum lands in 4 lanes.
__device__ __forceinline__ float reduce4h(const float p[4], int lane) {
    float m0 = merge2(p[0], p[1], lane, 8);
    float m1 = merge2(p[2], p[3], lane, 8);
    float r  = merge2(m0, m1, lane, 4);
    r += __shfl_xor_sync(FULL, r, 2);
    r += __shfl_xor_sync(FULL, r, 1);
    return r;
}

// fp32 -> fp16 table conversion (streaming); thread 0 also zeroes the output.
__global__ __launch_bounds__(256)
void sgns_convert(const float4* __restrict__ src, float* __restrict__ out) {
    const int n4 = VOCAB * DIM / 4;  // 3,200,000
    int i = blockIdx.x * blockDim.x + threadIdx.x;
    if (i == 0) out[0] = 0.0f;
    if (i < n4) {
        float4 v = __ldg(src + i);
        __half2 a = __floats2half2_rn(v.x, v.y);
        __half2 b = __floats2half2_rn(v.z, v.w);
        uint2 o;
        o.x = *reinterpret_cast<unsigned*>(&a);
        o.y = *reinterpret_cast<unsigned*>(&b);
        reinterpret_cast<uint2*>(g_emb_o_h)[i] = o;
    }
}

// 1 warp per batch row; half-warp per embedding row (uint4 = 8 halves per lane).
__global__ __launch_bounds__(128, 6)
void sgns_kernel(const float* __restrict__ emb_i,
                 const int*   __restrict__ iword,
                 const int*   __restrict__ owords,
                 const int*   __restrict__ nwords,
                 float*       __restrict__ out) {
    const int warp = (blockIdx.x * blockDim.x + threadIdx.x) >> 5;
    const int lane = threadIdx.x & 31;
    if (warp >= BATCH) return;
    const int hi  = lane >> 4;    // which of the 2 rows per load
    const int l15 = lane & 15;    // position within the row (16B chunk)

    // iv: this lane's 8-float slice of the input-word vector, as 4x half2
    const float* ivp = emb_i + (size_t)iword[warp] * DIM + l15 * 8;
    const float4 a0 = *reinterpret_cast<const float4*>(ivp);
    const float4 a1 = *reinterpret_cast<const float4*>(ivp + 4);
    __half2 iv[4];
    iv[0] = __floats2half2_rn(a0.x, a0.y);
    iv[1] = __floats2half2_rn(a0.z, a0.w);
    iv[2] = __floats2half2_rn(a1.x, a1.y);
    iv[3] = __floats2half2_rn(a1.z, a1.w);

    const int* __restrict__ ow = owords + warp * CTX;   // only 8-byte aligned; scalar loads
    const int* __restrict__ nw = nwords + warp * NNEG;  // 16-byte aligned (200*4B)

    float acc2  = 0.0f;   // rows counted 2x across the warp
    float acc4  = 0.0f;   // rows counted 4x
    float acc16 = 0.0f;   // rows counted 16x (uniform within half)

    // ---- positives: 10 rows = 5 warp-loads (scalar index loads: ow not 16B-aligned) ----
    {
        int i0 = ow[0 + hi];
        int i1 = ow[2 + hi];
        int i2 = ow[4 + hi];
        int i3 = ow[6 + hi];
        int i4 = ow[8 + hi];
        uint4 v0 = __ldg(row_h4(i0) + l15);
        uint4 v1 = __ldg(row_h4(i1) + l15);
        uint4 v2 = __ldg(row_h4(i2) + l15);
        uint4 v3 = __ldg(row_h4(i3) + l15);
        uint4 v4 = __ldg(row_h4(i4) + l15);

        float p[4];
        p[0] = dot8h2(iv, v0); p[1] = dot8h2(iv, v1);
        p[2] = dot8h2(iv, v2); p[3] = dot8h2(iv, v3);
        acc4 += log_sigmoid(reduce4h(p, lane));

        float q = dot8h2(iv, v4);
        q += __shfl_xor_sync(FULL, q, 8);
        q += __shfl_xor_sync(FULL, q, 4);
        q += __shfl_xor_sync(FULL, q, 2);
        q += __shfl_xor_sync(FULL, q, 1);
        acc16 += log_sigmoid(q);   // uniform within half
    }

    // ---- negatives: 12 batches of 16 rows, index loads pipelined one batch ahead ----
    int4 ia = *reinterpret_cast<const int4*>(nw);
    int4 ib = *reinterpret_cast<const int4*>(nw + 4);
    int4 ic = *reinterpret_cast<const int4*>(nw + 8);
    int4 id = *reinterpret_cast<const int4*>(nw + 12);

#pragma unroll 1
    for (int k = 0; k < 192; k += 16) {
        // Select this batch's 8 per-half indices, freeing ia..id.
        int i0 = hi ? ia.y : ia.x;
        int i1 = hi ? ia.w : ia.z;
        int i2 = hi ? ib.y : ib.x;
        int i3 = hi ? ib.w : ib.z;
        int i4 = hi ? ic.y : ic.x;
        int i5 = hi ? ic.w : ic.z;
        int i6 = hi ? id.y : id.x;
        int i7 = hi ? id.w : id.z;

        // Issue all 8 data loads (4KB/warp in flight).
        uint4 v0 = __ldg(row_h4(i0) + l15);
        uint4 v1 = __ldg(row_h4(i1) + l15);
        uint4 v2 = __ldg(row_h4(i2) + l15);
        uint4 v3 = __ldg(row_h4(i3) + l15);
        uint4 v4 = __ldg(row_h4(i4) + l15);
        uint4 v5 = __ldg(row_h4(i5) + l15);
        uint4 v6 = __ldg(row_h4(i6) + l15);
        uint4 v7 = __ldg(row_h4(i7) + l15);

        // Prefetch next batch's indices; latency overlaps this batch's compute.
        // Clamped on the last iteration (values discarded).
        const int ko = (k < 176) ? (k + 16) : 0;
        ia = *reinterpret_cast<const int4*>(nw + ko);
        ib = *reinterpret_cast<const int4*>(nw + ko + 4);
        ic = *reinterpret_cast<const int4*>(nw + ko + 8);
        id = *reinterpret_cast<const int4*>(nw + ko + 12);

        float p[8];
        p[0] = dot8h2(iv, v0); p[1] = dot8h2(iv, v1);
        p[2] = dot8h2(iv, v2); p[3] = dot8h2(iv, v3);
        p[4] = dot8h2(iv, v4); p[5] = dot8h2(iv, v5);
        p[6] = dot8h2(iv, v6); p[7] = dot8h2(iv, v7);

        acc2 += log_sigmoid(-reduce8h(p, lane));
    }

    // ---- remaining 8 negatives: 4 warp-loads ----
    {
        const int4 ta = *reinterpret_cast<const int4*>(nw + 192);
        const int4 tb = *reinterpret_cast<const int4*>(nw + 196);
        int i0 = hi ? ta.y : ta.x;
        int i1 = hi ? ta.w : ta.z;
        int i2 = hi ? tb.y : tb.x;
        int i3 = hi ? tb.w : tb.z;
        uint4 v0 = __ldg(row_h4(i0) + l15);
        uint4 v1 = __ldg(row_h4(i1) + l15);
        uint4 v2 = __ldg(row_h4(i2) + l15);
        uint4 v3 = __ldg(row_h4(i3) + l15);
        float p[4];
        p[0] = dot8h2(iv, v0); p[1] = dot8h2(iv, v1);
        p[2] = dot8h2(iv, v2); p[3] = dot8h2(iv, v3);
        acc4 += log_sigmoid(-reduce4h(p, lane));
    }

    // Combine redundancy-weighted accumulators, then full-warp sum.
    float a = fmaf(acc2, 0.5f, fmaf(acc4, 0.25f, acc16 * 0.0625f));
    a += __shfl_xor_sync(FULL, a, 16);
    a += __shfl_xor_sync(FULL, a, 8);
    a += __shfl_xor_sync(FULL, a, 4);
    a += __shfl_xor_sync(FULL, a, 2);
    a += __shfl_xor_sync(FULL, a, 1);

    if (lane == 0) {
        atomicAdd(out, -a * (1.0f / (float)(CTX * BATCH)));
    }
}

extern "C" void kernel_launch(void* const* d_in, const int* in_sizes, int n_in,
                              void* d_out, int out_size) {
    const float* emb_i  = (const float*)d_in[0];
    const float* emb_o  = (const float*)d_in[1];
    const int*   iword  = (const int*)d_in[2];
    const int*   owords = (const int*)d_in[3];
    const int*   nwords = (const int*)d_in[4];
    float* out = (float*)d_out;

    // Convert emb_o to fp16 scratch table (also zeroes out[0])
    const int n4 = VOCAB * DIM / 4;
    sgns_convert<<<(n4 + 255) / 256, 256>>>(reinterpret_cast<const float4*>(emb_o), out);

    // Main: 1 warp per batch row, 128-thread blocks for fine wave packing
    const int threads = 128;
    const int blocks = BATCH * 32 / threads;  // 1024
    sgns_kernel<<<blocks, threads>>>(emb_i, iword, owords, nwords, out);
}